// round 7
// baseline (speedup 1.0000x reference)
#include <cuda_runtime.h>
#include <math.h>

#define BB  512
#define TT  1024
#define TM  1023
#define FF  64
#define SN  128
#define HHD 128
#define G3  384
#define KC  192
#define HOR 24

// ---------------- scratch (device globals; allocation-free) ----------------
__device__ float g_hs [(size_t)BB * TM * SN];   // h_s, overwritten in-place -> h_snn
__device__ float g_xp [(size_t)BB * TM * G3];   // x_proj
__device__ float g_gru[(size_t)BB * TM * HHD];  // gru_out
__device__ float g_sc [(size_t)BB * TM];        // attention scores

// ============================================================================
// K1: h_s[b,t,c] = sum_f (x[b,t+1,f]-x[b,t,f]) * proj_w[c,f] + proj_b[c]
// ============================================================================
__global__ __launch_bounds__(256) void k1_hs(const float* __restrict__ x,
                                             const float* __restrict__ pw,
                                             const float* __restrict__ pb) {
    __shared__ float wsh[FF * 129];   // [f*129 + c]  transposed proj_w
    __shared__ float dsh[32 * 68];    // [row*68 + f] delta tile
    int b   = blockIdx.y;
    int t0  = blockIdx.x * 32;
    int tid = threadIdx.x;

    for (int i = tid; i < SN * FF; i += 256) {
        int c = i >> 6, f = i & 63;
        wsh[f * 129 + c] = pw[i];
    }
    for (int i = tid; i < 32 * FF; i += 256) {
        int row = i >> 6, f = i & 63;
        int t = t0 + row;
        float d = 0.f;
        if (t < TM) {
            const float* xb = x + ((size_t)b * TT + t) * FF + f;
            d = xb[FF] - xb[0];
        }
        dsh[row * 68 + f] = d;
    }
    __syncthreads();

    int c  = tid & 127;
    int rg = tid >> 7;            // 0..1 -> 16 t's each
    float bias = pb[c];
    float acc[16];
#pragma unroll
    for (int i = 0; i < 16; i++) acc[i] = bias;

#pragma unroll
    for (int f4 = 0; f4 < FF; f4 += 4) {
        float w0 = wsh[(f4 + 0) * 129 + c];
        float w1 = wsh[(f4 + 1) * 129 + c];
        float w2 = wsh[(f4 + 2) * 129 + c];
        float w3 = wsh[(f4 + 3) * 129 + c];
#pragma unroll
        for (int i = 0; i < 16; i++) {
            float4 d4 = *reinterpret_cast<const float4*>(&dsh[(rg * 16 + i) * 68 + f4]);
            acc[i] += w0 * d4.x + w1 * d4.y + w2 * d4.z + w3 * d4.w;
        }
    }
#pragma unroll
    for (int i = 0; i < 16; i++) {
        int t = t0 + rg * 16 + i;
        if (t < TM) g_hs[((size_t)b * TM + t) * SN + c] = acc[i];
    }
}

// ============================================================================
// K2: LIF SNN scan, in-place on g_hs. One thread per (b, channel) chain.
// ============================================================================
__global__ __launch_bounds__(128) void k2_snn(const float* __restrict__ be1,
                                              const float* __restrict__ be2) {
    int c = threadIdx.x;
    int b = blockIdx.x;
    float bt1 = fminf(fmaxf(be1[c], 0.f), 0.99f);
    float bt2 = fminf(fmaxf(be2[c], 0.f), 0.99f);
    float m1 = 0.f, s1 = 0.f, m2 = 0.f, s2 = 0.f;
    float* p = g_hs + (size_t)b * TM * SN + c;

    int t = 0;
    for (; t + 4 <= TM; t += 4) {
        float i0 = p[0], i1 = p[SN], i2 = p[2 * SN], i3 = p[3 * SN];
        m1 = bt1 * m1 + i0 - s1; s1 = (m1 > 1.f) ? 1.f : 0.f;
        m2 = bt2 * m2 + s1 - s2; s2 = (m2 > 1.f) ? 1.f : 0.f;
        p[0] = m2;
        m1 = bt1 * m1 + i1 - s1; s1 = (m1 > 1.f) ? 1.f : 0.f;
        m2 = bt2 * m2 + s1 - s2; s2 = (m2 > 1.f) ? 1.f : 0.f;
        p[SN] = m2;
        m1 = bt1 * m1 + i2 - s1; s1 = (m1 > 1.f) ? 1.f : 0.f;
        m2 = bt2 * m2 + s1 - s2; s2 = (m2 > 1.f) ? 1.f : 0.f;
        p[2 * SN] = m2;
        m1 = bt1 * m1 + i3 - s1; s1 = (m1 > 1.f) ? 1.f : 0.f;
        m2 = bt2 * m2 + s1 - s2; s2 = (m2 > 1.f) ? 1.f : 0.f;
        p[3 * SN] = m2;
        p += 4 * SN;
    }
    for (; t < TM; t++) {
        float iv = p[0];
        m1 = bt1 * m1 + iv - s1; s1 = (m1 > 1.f) ? 1.f : 0.f;
        m2 = bt2 * m2 + s1 - s2; s2 = (m2 > 1.f) ? 1.f : 0.f;
        p[0] = m2;
        p += SN;
    }
}

// ============================================================================
// K3: x_proj = [raw | h_snn] @ W_ih^T + b_ih.  M=523776, N=384, K=192.
// 128x128 tile, BK=16, 8x8 microtile, software-pipelined global loads.
// ============================================================================
__global__ __launch_bounds__(256) void k3_xproj(const float* __restrict__ x,
                                                const float* __restrict__ wih,
                                                const float* __restrict__ bih) {
    __shared__ float As[16 * 132];
    __shared__ float Bs[16 * 132];
    int m0  = blockIdx.y * 128;
    int n0  = blockIdx.x * 128;
    int tid = threadIdx.x;
    int lr  = tid >> 1;     // 0..127: row (A) / col (B) for loads
    int lq  = tid & 1;      // k-half (8 floats each)

    int m  = m0 + lr;
    int b  = m / TM;
    int t  = m - b * TM;
    const float* xrow = x + ((size_t)b * TT + t + 1) * FF;   // raw, k < 64
    const float* hrow = g_hs + (size_t)m * SN;               // h_snn, k >= 64
    const float* brow = wih + (size_t)(n0 + lr) * KC;

    int ty = tid >> 4, tx = tid & 15;
    float acc[8][8];
#pragma unroll
    for (int i = 0; i < 8; i++)
#pragma unroll
        for (int j = 0; j < 8; j++) acc[i][j] = 0.f;

    float4 a0, a1, bb0, bb1;
    {   // prologue load: ks = 0
        int k0 = lq * 8;
        a0  = *reinterpret_cast<const float4*>(xrow + k0);
        a1  = *reinterpret_cast<const float4*>(xrow + k0 + 4);
        bb0 = *reinterpret_cast<const float4*>(brow + k0);
        bb1 = *reinterpret_cast<const float4*>(brow + k0 + 4);
    }

    for (int ks = 0; ks < 12; ks++) {
        int kk = lq * 8;
        As[(kk + 0) * 132 + lr] = a0.x;  As[(kk + 1) * 132 + lr] = a0.y;
        As[(kk + 2) * 132 + lr] = a0.z;  As[(kk + 3) * 132 + lr] = a0.w;
        As[(kk + 4) * 132 + lr] = a1.x;  As[(kk + 5) * 132 + lr] = a1.y;
        As[(kk + 6) * 132 + lr] = a1.z;  As[(kk + 7) * 132 + lr] = a1.w;
        Bs[(kk + 0) * 132 + lr] = bb0.x; Bs[(kk + 1) * 132 + lr] = bb0.y;
        Bs[(kk + 2) * 132 + lr] = bb0.z; Bs[(kk + 3) * 132 + lr] = bb0.w;
        Bs[(kk + 4) * 132 + lr] = bb1.x; Bs[(kk + 5) * 132 + lr] = bb1.y;
        Bs[(kk + 6) * 132 + lr] = bb1.z; Bs[(kk + 7) * 132 + lr] = bb1.w;
        __syncthreads();

        if (ks < 11) {   // prefetch next k-tile (latency hidden by compute)
            int k0 = (ks + 1) * 16 + lq * 8;
            if (k0 < 64) {
                a0 = *reinterpret_cast<const float4*>(xrow + k0);
                a1 = *reinterpret_cast<const float4*>(xrow + k0 + 4);
            } else {
                a0 = *reinterpret_cast<const float4*>(hrow + k0 - 64);
                a1 = *reinterpret_cast<const float4*>(hrow + k0 - 60);
            }
            bb0 = *reinterpret_cast<const float4*>(brow + k0);
            bb1 = *reinterpret_cast<const float4*>(brow + k0 + 4);
        }

#pragma unroll
        for (int k2 = 0; k2 < 16; k2++) {
            float4 av0 = *reinterpret_cast<const float4*>(&As[k2 * 132 + ty * 8]);
            float4 av1 = *reinterpret_cast<const float4*>(&As[k2 * 132 + ty * 8 + 4]);
            float4 bv0 = *reinterpret_cast<const float4*>(&Bs[k2 * 132 + tx * 8]);
            float4 bv1 = *reinterpret_cast<const float4*>(&Bs[k2 * 132 + tx * 8 + 4]);
            float ar[8] = {av0.x, av0.y, av0.z, av0.w, av1.x, av1.y, av1.z, av1.w};
            float br[8] = {bv0.x, bv0.y, bv0.z, bv0.w, bv1.x, bv1.y, bv1.z, bv1.w};
#pragma unroll
            for (int i = 0; i < 8; i++)
#pragma unroll
                for (int j = 0; j < 8; j++) acc[i][j] += ar[i] * br[j];
        }
        __syncthreads();
    }

    float bias[8];
#pragma unroll
    for (int j = 0; j < 8; j++) bias[j] = bih[n0 + tx * 8 + j];
#pragma unroll
    for (int i = 0; i < 8; i++) {
        float* orow = g_xp + (size_t)(m0 + ty * 8 + i) * G3 + n0 + tx * 8;
#pragma unroll
        for (int j = 0; j < 8; j++) orow[j] = acc[i][j] + bias[j];
    }
}

// ============================================================================
// K4: GRU scan. Persistent: 128 CTAs x 4 batch rows. 768 threads =
// 384 outputs x 2 k-halves; W_hh rows live in registers (64 f32/thread).
// ============================================================================
__global__ __launch_bounds__(768, 1) void k4_gru(const float* __restrict__ whh,
                                                 const float* __restrict__ bhh) {
    __shared__ float hsh[4][HHD];
    __shared__ float ghsh[4][G3];
    __shared__ float xpsh[2][4][G3];

    int tid  = threadIdx.x;
    int half = (tid >= 384) ? 1 : 0;
    int j    = tid - half * 384;
    int b0   = blockIdx.x * 4;

    float4 w4[16];
    const float4* wp = reinterpret_cast<const float4*>(whh + (size_t)j * HHD + half * 64);
#pragma unroll
    for (int i = 0; i < 16; i++) w4[i] = wp[i];
    float bj = bhh[j];

    for (int i = tid; i < 4 * HHD; i += 768) hsh[i >> 7][i & 127] = 0.f;
    // preload xp for t = 0
    xpsh[0][half][j]     = g_xp[((size_t)(b0 + half) * TM) * G3 + j];
    xpsh[0][2 + half][j] = g_xp[((size_t)(b0 + 2 + half) * TM) * G3 + j];
    __syncthreads();

    int r0 = tid >> 7;       // update-phase mapping (tid < 512)
    int cc = tid & 127;

    for (int t = 0; t < TM; t++) {
        int cur = t & 1, nb = cur ^ 1;

        float pf0 = 0.f, pf1 = 0.f;
        if (t + 1 < TM) {
            pf0 = g_xp[((size_t)(b0 + half) * TM + t + 1) * G3 + j];
            pf1 = g_xp[((size_t)(b0 + 2 + half) * TM + t + 1) * G3 + j];
        }

        float a0 = 0.f, a1 = 0.f, a2 = 0.f, a3 = 0.f;
        const float* h0 = &hsh[0][half * 64];
        const float* h1 = &hsh[1][half * 64];
        const float* h2 = &hsh[2][half * 64];
        const float* h3 = &hsh[3][half * 64];
#pragma unroll
        for (int kq = 0; kq < 16; kq++) {
            float4 w = w4[kq];
            float4 v0 = *reinterpret_cast<const float4*>(h0 + kq * 4);
            a0 += w.x * v0.x + w.y * v0.y + w.z * v0.z + w.w * v0.w;
            float4 v1 = *reinterpret_cast<const float4*>(h1 + kq * 4);
            a1 += w.x * v1.x + w.y * v1.y + w.z * v1.z + w.w * v1.w;
            float4 v2 = *reinterpret_cast<const float4*>(h2 + kq * 4);
            a2 += w.x * v2.x + w.y * v2.y + w.z * v2.z + w.w * v2.w;
            float4 v3 = *reinterpret_cast<const float4*>(h3 + kq * 4);
            a3 += w.x * v3.x + w.y * v3.y + w.z * v3.z + w.w * v3.w;
        }

        xpsh[nb][half][j]     = pf0;     // stash prefetch (read next step)
        xpsh[nb][2 + half][j] = pf1;
        if (half == 1) {
            ghsh[0][j] = a0; ghsh[1][j] = a1; ghsh[2][j] = a2; ghsh[3][j] = a3;
        }
        __syncthreads();
        if (half == 0) {
            ghsh[0][j] = a0 + ghsh[0][j] + bj;
            ghsh[1][j] = a1 + ghsh[1][j] + bj;
            ghsh[2][j] = a2 + ghsh[2][j] + bj;
            ghsh[3][j] = a3 + ghsh[3][j] + bj;
        }
        __syncthreads();

        if (tid < 512) {
            float xr = xpsh[cur][r0][cc];
            float xz = xpsh[cur][r0][cc + 128];
            float xn = xpsh[cur][r0][cc + 256];
            float hr = ghsh[r0][cc];
            float hz = ghsh[r0][cc + 128];
            float hn = ghsh[r0][cc + 256];
            float rr = 1.f / (1.f + __expf(-(xr + hr)));
            float zg = 1.f / (1.f + __expf(-(xz + hz)));
            float nn = tanhf(xn + rr * hn);
            float hold = hsh[r0][cc];
            float hnew = (1.f - zg) * nn + zg * hold;
            hsh[r0][cc] = hnew;
            g_gru[((size_t)(b0 + r0) * TM + t) * HHD + cc] = hnew;
        }
        __syncthreads();
    }
}

// ============================================================================
// K5: scores = relu(gru @ w1^T + b1) @ w2^T + b2.  Block: one b x 64 t's.
// ============================================================================
__global__ __launch_bounds__(256) void k5_scores(const float* __restrict__ w1,
                                                 const float* __restrict__ ab1,
                                                 const float* __restrict__ w2,
                                                 const float* __restrict__ ab2) {
    __shared__ float gsh[64 * 132];   // gru tile [tl*132 + k]
    __shared__ float wred[8][16];     // per-warp partial scores
    int b   = blockIdx.y;
    int t0  = blockIdx.x * 64;
    int tid = threadIdx.x;

    for (int i = tid; i < 64 * 128; i += 256) {
        int tl = i >> 7, k = i & 127;
        int t = t0 + tl;
        gsh[tl * 132 + k] = (t < TM) ? g_gru[((size_t)b * TM + t) * HHD + k] : 0.f;
    }
    __syncthreads();

    int n  = tid & 63;
    int tg = tid >> 6;                  // 4 groups x 16 t's
    float bn  = ab1[n];
    float w2n = w2[n];

    float hid[16];
#pragma unroll
    for (int i = 0; i < 16; i++) hid[i] = bn;

    const float* wrow = w1 + (size_t)n * HHD;
#pragma unroll 8
    for (int k4 = 0; k4 < 32; k4++) {
        float4 wv = *reinterpret_cast<const float4*>(wrow + k4 * 4);
#pragma unroll
        for (int i = 0; i < 16; i++) {
            float4 gv = *reinterpret_cast<const float4*>(&gsh[(tg * 16 + i) * 132 + k4 * 4]);
            hid[i] += wv.x * gv.x + wv.y * gv.y + wv.z * gv.z + wv.w * gv.w;
        }
    }

    // per-thread contribution, warp-reduce over the 32 n-lanes of this warp
    int wid = tid >> 5;
#pragma unroll
    for (int i = 0; i < 16; i++) {
        float sv = fmaxf(hid[i], 0.f) * w2n;
#pragma unroll
        for (int o = 16; o; o >>= 1) sv += __shfl_xor_sync(0xffffffffu, sv, o);
        if ((tid & 31) == 0) wred[wid][i] = sv;
    }
    __syncthreads();

    if (tid < 64) {                      // t_local = tid; warps 2*tg, 2*tg+1
        int tgg = tid >> 4, ii = tid & 15;
        float s = wred[2 * tgg][ii] + wred[2 * tgg + 1][ii] + ab2[0];
        int t = t0 + tid;
        if (t < TM) g_sc[(size_t)b * TM + t] = s;
    }
}

// ============================================================================
// K6: softmax over t, weighted pool of gru_out, fused head. One block per b.
// ============================================================================
__global__ __launch_bounds__(128) void k6_pool(const float* __restrict__ hw,
                                               const float* __restrict__ hb,
                                               float* __restrict__ out) {
    __shared__ float psh[TM];
    __shared__ float red[16];
    __shared__ float hann[HHD];
    int b   = blockIdx.x;
    int tid = threadIdx.x;
    const float* sc = g_sc + (size_t)b * TM;

    float mx = -1e30f;
    for (int t = tid; t < TM; t += 128) mx = fmaxf(mx, sc[t]);
#pragma unroll
    for (int o = 16; o; o >>= 1) mx = fmaxf(mx, __shfl_xor_sync(0xffffffffu, mx, o));
    if ((tid & 31) == 0) red[tid >> 5] = mx;
    __syncthreads();
    mx = fmaxf(fmaxf(red[0], red[1]), fmaxf(red[2], red[3]));

    float sm = 0.f;
    for (int t = tid; t < TM; t += 128) {
        float e = __expf(sc[t] - mx);
        psh[t] = e;
        sm += e;
    }
#pragma unroll
    for (int o = 16; o; o >>= 1) sm += __shfl_xor_sync(0xffffffffu, sm, o);
    if ((tid & 31) == 0) red[8 + (tid >> 5)] = sm;
    __syncthreads();
    sm = red[8] + red[9] + red[10] + red[11];
    float inv = 1.f / sm;

    const float* gb = g_gru + (size_t)b * TM * HHD + tid;   // tid == channel
    float acc = 0.f;
    int t = 0;
    for (; t + 4 <= TM; t += 4) {
        float g0 = gb[(size_t)(t + 0) * HHD];
        float g1 = gb[(size_t)(t + 1) * HHD];
        float g2 = gb[(size_t)(t + 2) * HHD];
        float g3 = gb[(size_t)(t + 3) * HHD];
        acc += psh[t] * g0 + psh[t + 1] * g1 + psh[t + 2] * g2 + psh[t + 3] * g3;
    }
    for (; t < TM; t++) acc += psh[t] * gb[(size_t)t * HHD];
    hann[tid] = acc * inv;
    __syncthreads();

    if (tid < HOR) {
        float s = hb[tid];
        const float* wr = hw + tid * HHD;
#pragma unroll 4
        for (int c = 0; c < HHD; c++) s += hann[c] * wr[c];
        out[b * HOR + tid] = s;
    }
}

// ============================================================================
extern "C" void kernel_launch(void* const* d_in, const int* in_sizes, int n_in,
                              void* d_out, int out_size) {
    const float* x       = (const float*)d_in[0];
    const float* proj_w  = (const float*)d_in[1];
    const float* proj_b  = (const float*)d_in[2];
    const float* beta1   = (const float*)d_in[3];
    const float* beta2   = (const float*)d_in[4];
    const float* gw_ih   = (const float*)d_in[5];
    const float* gw_hh   = (const float*)d_in[6];
    const float* gb_ih   = (const float*)d_in[7];
    const float* gb_hh   = (const float*)d_in[8];
    const float* attn_w1 = (const float*)d_in[9];
    const float* attn_b1 = (const float*)d_in[10];
    const float* attn_w2 = (const float*)d_in[11];
    const float* attn_b2 = (const float*)d_in[12];
    const float* head_w  = (const float*)d_in[13];
    const float* head_b  = (const float*)d_in[14];
    float* out = (float*)d_out;

    dim3 g1(32, BB);
    k1_hs<<<g1, 256>>>(x, proj_w, proj_b);
    k2_snn<<<BB, 128>>>(beta1, beta2);
    dim3 g3(3, 4092);                       // 384/128 n-tiles x 523776/128 m-tiles
    k3_xproj<<<g3, 256>>>(x, gw_ih, gb_ih);
    k4_gru<<<128, 768>>>(gw_hh, gb_hh);
    dim3 g5(16, BB);                        // ceil(1023/64) t-tiles x B
    k5_scores<<<g5, 256>>>(attn_w1, attn_b1, attn_w2, attn_b2);
    k6_pool<<<BB, 128>>>(head_w, head_b, out);
}